// round 1
// baseline (speedup 1.0000x reference)
#include <cuda_runtime.h>
#include <cstdint>

// Problem constants (fixed shapes from reference setup_inputs)
#define NPTS 16384          // B*H*W = 16*32*32
#define KCODES 8192
#define DDIM 128
#define HWSZ 1024           // H*W
#define NSPLIT 4            // K-split for argmin load balance
#define KPER (KCODES / NSPLIT)

// Output layout (concatenated flattened outputs, all float32):
// z_q_st (B,D,H,W) | indices (B,H,W) | new_codebook (K,D) | new_count (K) | new_weight (K,D)
#define O_ZQ  0
#define O_IDX 2097152
#define O_CB  2113536
#define O_CNT 3162112
#define O_WT  3170304

// Device-global scratch (no allocations allowed in kernel_launch)
__device__ float g_cnorm[KCODES];
__device__ float g_cbT[DDIM * KCODES];      // transposed codebook [d][k], 4MB
__device__ int   g_idx[NPTS];
__device__ float g_counts[KCODES];
__device__ float g_dw[KCODES * DDIM];       // 4MB
__device__ float g_pv[NSPLIT * NPTS];       // partial min values per split
__device__ int   g_pi[NSPLIT * NPTS];       // partial min indices per split

// ---------------------------------------------------------------------------
// Kernel 1: codebook norms + zero the accumulators (must re-zero every replay)
// grid = K, block = 128
__global__ void prep_kernel(const float* __restrict__ cb) {
    int k = blockIdx.x;
    int t = threadIdx.x;
    float v = cb[k * DDIM + t];
    g_dw[k * DDIM + t] = 0.0f;
    float sq = v * v;
    #pragma unroll
    for (int o = 16; o > 0; o >>= 1) sq += __shfl_down_sync(0xffffffffu, sq, o);
    __shared__ float red[4];
    if ((t & 31) == 0) red[t >> 5] = sq;
    __syncthreads();
    if (t == 0) {
        g_cnorm[k] = red[0] + red[1] + red[2] + red[3];
        g_counts[k] = 0.0f;
    }
}

// ---------------------------------------------------------------------------
// Kernel 2: transpose codebook -> g_cbT[d][k]  (writes coalesced)
// grid = 128 (one d per block), block = 256
__global__ void transpose_kernel(const float* __restrict__ cb) {
    int d = blockIdx.x;
    for (int k = threadIdx.x; k < KCODES; k += blockDim.x)
        g_cbT[d * KCODES + k] = cb[k * DDIM + d];
}

// ---------------------------------------------------------------------------
// Kernel 3: argmin distance GEMM.
// grid = (NPTS/64, NSPLIT), block = 256. Each block: 64 points x KPER codes.
// Minimizes  cnorm[k] - 2 * dot(z_n, c_k)   (||z||^2 is row-constant).
#define BM 64
#define BN 32
__global__ __launch_bounds__(256) void argmin_kernel(const float* __restrict__ z) {
    __shared__ float zs[DDIM * BM];   // 32KB, d-major: zs[d*64 + p]
    __shared__ float cs[DDIM * BN];   // 16KB, d-major: cs[d*32 + q]

    const int tid = threadIdx.x;
    const int tp = tid & 15;          // point group (4 points each)
    const int tk = tid >> 4;          // code group (2 codes each)

    const int pbase = blockIdx.x * BM;
    const int b = pbase >> 10;        // BM=64 divides HW=1024: tile within one image
    const int hw0 = pbase & (HWSZ - 1);
    const int kbeg = blockIdx.y * KPER;

    // Load z tile: z_e[(b*128+d)*1024 + hw0+p] -> zs[d][p]; fully coalesced.
    const float* zb = z + ((size_t)b * DDIM) * HWSZ + hw0;
    for (int i = tid; i < DDIM * BM; i += 256) {
        int d = i >> 6, p = i & 63;
        zs[i] = zb[(size_t)d * HWSZ + p];
    }

    float minv[4];
    int   mini[4];
    #pragma unroll
    for (int i = 0; i < 4; i++) { minv[i] = 3.402823466e38f; mini[i] = 0; }

    for (int kt = 0; kt < KPER; kt += BN) {
        __syncthreads();  // protect cs reuse (also covers zs readiness on iter 0)
        // Load code tile from transposed codebook: coalesced, conflict-free STS.
        const float* cbt = g_cbT + kbeg + kt;
        for (int i = tid; i < DDIM * BN; i += 256) {
            int d = i >> 5, q = i & 31;
            cs[i] = cbt[(size_t)d * KCODES + q];
        }
        __syncthreads();

        float acc00 = 0.f, acc01 = 0.f, acc10 = 0.f, acc11 = 0.f;
        float acc20 = 0.f, acc21 = 0.f, acc30 = 0.f, acc31 = 0.f;
        #pragma unroll 8
        for (int d = 0; d < DDIM; d++) {
            const float4 zf = *(const float4*)(zs + d * 64 + tp * 4);
            const float2 cf = *(const float2*)(cs + d * 32 + tk * 2);
            acc00 += zf.x * cf.x;  acc01 += zf.x * cf.y;
            acc10 += zf.y * cf.x;  acc11 += zf.y * cf.y;
            acc20 += zf.z * cf.x;  acc21 += zf.z * cf.y;
            acc30 += zf.w * cf.x;  acc31 += zf.w * cf.y;
        }

        // Distances and running min (strict < keeps first/lowest index since
        // kk ascends across j and kt).
        {
            const int k0 = kbeg + kt + tk * 2;
            const float cn0 = g_cnorm[k0];
            const float cn1 = g_cnorm[k0 + 1];
            float dj0, dj1;
            dj0 = cn0 - 2.0f * acc00; dj1 = cn1 - 2.0f * acc01;
            if (dj0 < minv[0]) { minv[0] = dj0; mini[0] = k0; }
            if (dj1 < minv[0]) { minv[0] = dj1; mini[0] = k0 + 1; }
            dj0 = cn0 - 2.0f * acc10; dj1 = cn1 - 2.0f * acc11;
            if (dj0 < minv[1]) { minv[1] = dj0; mini[1] = k0; }
            if (dj1 < minv[1]) { minv[1] = dj1; mini[1] = k0 + 1; }
            dj0 = cn0 - 2.0f * acc20; dj1 = cn1 - 2.0f * acc21;
            if (dj0 < minv[2]) { minv[2] = dj0; mini[2] = k0; }
            if (dj1 < minv[2]) { minv[2] = dj1; mini[2] = k0 + 1; }
            dj0 = cn0 - 2.0f * acc30; dj1 = cn1 - 2.0f * acc31;
            if (dj0 < minv[3]) { minv[3] = dj0; mini[3] = k0; }
            if (dj1 < minv[3]) { minv[3] = dj1; mini[3] = k0 + 1; }
        }
    }

    // Cross-thread reduction per point over the 16 tk groups (reuse zs).
    __syncthreads();
    float* rv = zs;                       // [64][16]
    int*   ri = (int*)(zs + 64 * 16);     // [64][16]
    #pragma unroll
    for (int i = 0; i < 4; i++) {
        rv[(tp * 4 + i) * 16 + tk] = minv[i];
        ri[(tp * 4 + i) * 16 + tk] = mini[i];
    }
    __syncthreads();
    if (tid < 64) {
        float bv = rv[tid * 16];
        int   bi = ri[tid * 16];
        #pragma unroll
        for (int t = 1; t < 16; t++) {
            float v = rv[tid * 16 + t];
            int  ii = ri[tid * 16 + t];
            if (v < bv || (v == bv && ii < bi)) { bv = v; bi = ii; }
        }
        g_pv[blockIdx.y * NPTS + pbase + tid] = bv;
        g_pi[blockIdx.y * NPTS + pbase + tid] = bi;
    }
}

// ---------------------------------------------------------------------------
// Kernel 4: reduce the NSPLIT partials (lexicographic: first lowest index on tie)
__global__ void reduce_idx_kernel() {
    int n = blockIdx.x * blockDim.x + threadIdx.x;
    if (n >= NPTS) return;
    float bv = g_pv[n];
    int   bi = g_pi[n];
    #pragma unroll
    for (int s = 1; s < NSPLIT; s++) {
        float v = g_pv[s * NPTS + n];
        int  ii = g_pi[s * NPTS + n];
        if (v < bv || (v == bv && ii < bi)) { bv = v; bi = ii; }
    }
    g_idx[n] = bi;
}

// ---------------------------------------------------------------------------
// Kernel 5: segment sums via global atomics. grid = NPTS, block = 128.
__global__ void accum_kernel(const float* __restrict__ z) {
    int n = blockIdx.x;
    int d = threadIdx.x;
    int idx = g_idx[n];
    int b = n >> 10, hw = n & (HWSZ - 1);
    float zv = z[((size_t)b * DDIM + d) * HWSZ + hw];
    atomicAdd(&g_dw[idx * DDIM + d], zv);
    if (d == 0) atomicAdd(&g_counts[idx], 1.0f);
}

// ---------------------------------------------------------------------------
// Kernel 6: EMA finalize -> new_weight, new_codebook, new_count. grid=K, block=128
__global__ void finalize_kernel(const float* __restrict__ ema_count,
                                const float* __restrict__ ema_weight,
                                float* __restrict__ out) {
    int k = blockIdx.x;
    int d = threadIdx.x;
    float cnt = ema_count[k] * 0.99f + 0.01f * g_counts[k];
    float w = ema_weight[(size_t)k * DDIM + d] * 0.99f + 0.01f * g_dw[(size_t)k * DDIM + d];
    out[O_WT + (size_t)k * DDIM + d] = w;
    out[O_CB + (size_t)k * DDIM + d] = w / fmaxf(cnt, 1.0f);
    if (d == 0) out[O_CNT + k] = cnt;
}

// ---------------------------------------------------------------------------
// Kernel 7: z_q straight-through output (exact fp emulation: ze + (zq - ze)).
// grid = B*D = 2048, block = 256
__global__ void zq_kernel(const float* __restrict__ z,
                          const float* __restrict__ cb,
                          float* __restrict__ out) {
    int bd = blockIdx.x;              // bd = b*128 + d
    int b = bd >> 7;
    int d = bd & 127;
    for (int hw = threadIdx.x; hw < HWSZ; hw += blockDim.x) {
        int n = b * HWSZ + hw;
        float ze = z[(size_t)bd * HWSZ + hw];
        float zq = cb[(size_t)g_idx[n] * DDIM + d];
        out[O_ZQ + (size_t)bd * HWSZ + hw] = ze + (zq - ze);
    }
}

// Kernel 8: indices output (cast to float)
__global__ void idxout_kernel(float* __restrict__ out) {
    int n = blockIdx.x * blockDim.x + threadIdx.x;
    if (n < NPTS) out[O_IDX + n] = (float)g_idx[n];
}

// ---------------------------------------------------------------------------
extern "C" void kernel_launch(void* const* d_in, const int* in_sizes, int n_in,
                              void* d_out, int out_size) {
    const float* z_e        = (const float*)d_in[0];   // (16,128,32,32)
    const float* codebook   = (const float*)d_in[1];   // (8192,128)
    const float* ema_count  = (const float*)d_in[2];   // (8192,)
    const float* ema_weight = (const float*)d_in[3];   // (8192,128)
    float* out = (float*)d_out;

    prep_kernel<<<KCODES, 128>>>(codebook);
    transpose_kernel<<<DDIM, 256>>>(codebook);

    dim3 agrid(NPTS / BM, NSPLIT);
    argmin_kernel<<<agrid, 256>>>(z_e);

    reduce_idx_kernel<<<(NPTS + 255) / 256, 256>>>();
    accum_kernel<<<NPTS, 128>>>(z_e);
    finalize_kernel<<<KCODES, 128>>>(ema_count, ema_weight, out);
    zq_kernel<<<2048, 256>>>(z_e, codebook, out);
    idxout_kernel<<<(NPTS + 255) / 256, 256>>>(out);
}

// round 3
// speedup vs baseline: 3.2911x; 3.2911x over previous
#include <cuda_runtime.h>
#include <cuda_fp16.h>
#include <cstdint>

// ---------------------------------------------------------------- constants
#define NPTS    16384
#define KCODES  8192
#define DDIM    128
#define HWSZ    1024
#define MTILE   128              // points per CTA
#define CTILE   256              // codes per CTA code-tile
#define NCTILES (KCODES / CTILE) // 32
#define NCHUNK  6                // k-chunks of 64 (extended K = 384)
#define NSTAGES (NCTILES * NCHUNK)
#define ZSTRIDE 392              // halves per zs row (384 + pad) -> conflict-free frags
#define BSTRIDE 72               // halves per B row (64 + pad)   -> conflict-free frags
#define BUFB    (CTILE * BSTRIDE * 2)  // 36864 bytes per B buffer

// Output layout (concatenated float32 outputs)
#define O_ZQ  0
#define O_IDX 2097152
#define O_CB  2113536
#define O_CNT 3162112
#define O_WT  3170304

// ---------------------------------------------------------------- scratch
__device__ float  g_cnorm[KCODES];
__device__ __half g_bext[6u * KCODES * 64];   // [chunk][code][64] fp16: hi0,hi1,lo0,lo1,hi0,hi1
__device__ int    g_idx[NPTS];
__device__ float  g_counts[KCODES];
__device__ float  g_dw[KCODES * DDIM];

// ---------------------------------------------------------------- helpers
__device__ __forceinline__ uint32_t smem_u32(const void* p) {
    uint32_t a;
    asm("{ .reg .u64 t; cvta.to.shared.u64 t, %1; cvt.u32.u64 %0, t; }" : "=r"(a) : "l"(p));
    return a;
}
__device__ __forceinline__ void cp_async16(uint32_t dst, const void* src) {
    asm volatile("cp.async.cg.shared.global [%0], [%1], 16;" :: "r"(dst), "l"(src) : "memory");
}
#define CP_COMMIT() asm volatile("cp.async.commit_group;" ::: "memory")
#define CP_WAIT1()  asm volatile("cp.async.wait_group 1;" ::: "memory")
#define CP_WAIT0()  asm volatile("cp.async.wait_group 0;" ::: "memory")

#define MMA16816(c, a0, a1, a2, a3, b0, b1)                                  \
    asm volatile("mma.sync.aligned.m16n8k16.row.col.f32.f16.f16.f32 "        \
                 "{%0,%1,%2,%3}, {%4,%5,%6,%7}, {%8,%9}, {%0,%1,%2,%3};"     \
                 : "+f"((c)[0]), "+f"((c)[1]), "+f"((c)[2]), "+f"((c)[3])    \
                 : "r"(a0), "r"(a1), "r"(a2), "r"(a3), "r"(b0), "r"(b1))

// ---------------------------------------------------------------- prep kernels
__global__ void prep_kernel(const float* __restrict__ cb) {
    int k = blockIdx.x, t = threadIdx.x;
    float v = cb[k * DDIM + t];
    g_dw[k * DDIM + t] = 0.0f;
    float sq = v * v;
    #pragma unroll
    for (int o = 16; o > 0; o >>= 1) sq += __shfl_down_sync(0xffffffffu, sq, o);
    __shared__ float red[4];
    if ((t & 31) == 0) red[t >> 5] = sq;
    __syncthreads();
    if (t == 0) { g_cnorm[k] = red[0] + red[1] + red[2] + red[3]; g_counts[k] = 0.0f; }
}

// fp16 hi/lo split of the codebook into [chunk][code][64] rows (128B each)
__global__ void bext_kernel(const float* __restrict__ cb) {
    int i = blockIdx.x * blockDim.x + threadIdx.x;
    int k = i >> 7, d = i & 127;
    float c = cb[i];
    __half h = __float2half_rn(c);
    __half l = __float2half_rn(c - __half2float(h));
    int half_ = d >> 6, pos = d & 63;
    size_t ro = (size_t)k * 64 + pos;
    const size_t BS = (size_t)KCODES * 64;
    g_bext[(size_t)half_ * BS + ro] = h;   // chunks 0,1: c_hi
    g_bext[(2 + half_) * BS + ro]   = l;   // chunks 2,3: c_lo
    g_bext[(4 + half_) * BS + ro]   = h;   // chunks 4,5: c_hi
}

// ---------------------------------------------------------------- argmin (HMMA)
// grid = 128 CTAs, block = 256 (8 warps: 2 in M x 4 in N), warp tile 64x64.
__global__ void __launch_bounds__(256, 1) argmin_kernel(const float* __restrict__ z) {
    extern __shared__ char smem[];
    __half* zs = (__half*)smem;                                   // 128*392*2 = 100352 B
    char*   bbase = smem + MTILE * ZSTRIDE * 2;                   // 2 x 36864 B
    float*  cnorm_s = (float*)(bbase + 2 * BUFB);                 // 32768 B

    const int tid = threadIdx.x;
    const int lane = tid & 31, wid = tid >> 5;
    const int wm = wid & 1;        // m block (64 rows)
    const int wn = wid >> 1;       // n block (64 cols)

    // ---- stage z tile: build fp16 hi/hi/lo extended rows (one-time)
    const int pbase = blockIdx.x * MTILE;
    const int b = pbase >> 10, hw0 = pbase & (HWSZ - 1);
    const float* zb = z + (size_t)b * DDIM * HWSZ + hw0;
    for (int i = tid; i < DDIM * MTILE; i += 256) {
        int d = i >> 7, p = i & 127;
        float v = zb[(size_t)d * HWSZ + p];
        __half h = __float2half_rn(v);
        __half l = __float2half_rn(v - __half2float(h));
        zs[p * ZSTRIDE + d]       = h;   // pairs with c_hi (chunks 0,1)
        zs[p * ZSTRIDE + 128 + d] = h;   // pairs with c_lo (chunks 2,3)
        zs[p * ZSTRIDE + 256 + d] = l;   // pairs with c_hi (chunks 4,5)
    }
    for (int i = tid; i < KCODES; i += 256) cnorm_s[i] = g_cnorm[i];

    const uint32_t bb32 = smem_u32(bbase);

    // ---- producer: one 256x64-half B chunk per stage via cp.async
    auto issue = [&](int s) {
        int ct = s / NCHUNK, c = s - ct * NCHUNK;
        const char* src = (const char*)(g_bext + ((size_t)c * KCODES + (size_t)ct * CTILE) * 64);
        uint32_t dst = bb32 + (uint32_t)(s & 1) * BUFB;
        #pragma unroll
        for (int i = 0; i < 8; i++) {
            int idx = tid + i * 256;                 // 0..2047 16B chunks
            cp_async16(dst + (uint32_t)(idx >> 3) * 144u + (uint32_t)(idx & 7) * 16u,
                       src + (size_t)idx * 16);
        }
        CP_COMMIT();
    };

    float acc[4][8][4];
    float minv[8];
    int   mini[8];
    #pragma unroll
    for (int s = 0; s < 8; s++) { minv[s] = 3.402823466e38f; mini[s] = 0; }

    issue(0);

    const __half* zrowbase = zs + (wm * 64 + (lane >> 2)) * ZSTRIDE + (lane & 3) * 2;

    for (int s = 0; s < NSTAGES; s++) {
        const int ct = s / NCHUNK, c = s - ct * NCHUNK;
        if (s + 1 < NSTAGES) { issue(s + 1); CP_WAIT1(); }
        else                 { CP_WAIT0(); }
        __syncthreads();

        if (c == 0) {
            #pragma unroll
            for (int mt = 0; mt < 4; mt++)
                #pragma unroll
                for (int nt = 0; nt < 8; nt++)
                    #pragma unroll
                    for (int r = 0; r < 4; r++) acc[mt][nt][r] = 0.0f;
        }

        const __half* bp = (const __half*)(bbase + (s & 1) * BUFB);
        const __half* brow = bp + (wn * 64 + (lane >> 2)) * BSTRIDE + (lane & 3) * 2;

        #pragma unroll
        for (int ks = 0; ks < 4; ks++) {
            const __half* ap = zrowbase + c * 64 + ks * 16;
            uint32_t a[4][4];
            #pragma unroll
            for (int mt = 0; mt < 4; mt++) {
                a[mt][0] = *(const uint32_t*)(ap + (mt * 16) * ZSTRIDE);
                a[mt][1] = *(const uint32_t*)(ap + (mt * 16 + 8) * ZSTRIDE);
                a[mt][2] = *(const uint32_t*)(ap + (mt * 16) * ZSTRIDE + 8);
                a[mt][3] = *(const uint32_t*)(ap + (mt * 16 + 8) * ZSTRIDE + 8);
            }
            #pragma unroll
            for (int nt = 0; nt < 8; nt++) {
                const __half* bq = brow + (nt * 8) * BSTRIDE + ks * 16;
                uint32_t b0 = *(const uint32_t*)bq;
                uint32_t b1 = *(const uint32_t*)(bq + 8);
                #pragma unroll
                for (int mt = 0; mt < 4; mt++)
                    MMA16816(acc[mt][nt], a[mt][0], a[mt][1], a[mt][2], a[mt][3], b0, b1);
            }
        }

        if (c == NCHUNK - 1) {
            // epilogue: dist = cnorm - 2*dot; running first-argmin in registers.
            const int code0 = ct * CTILE + wn * 64 + (lane & 3) * 2;
            #pragma unroll
            for (int nt = 0; nt < 8; nt++) {
                const int kk = code0 + nt * 8;
                const float2 cn = *(const float2*)(cnorm_s + kk);
                #pragma unroll
                for (int mt = 0; mt < 4; mt++) {
                    const int s0 = mt * 2;
                    float d0 = fmaf(-2.0f, acc[mt][nt][0], cn.x);
                    float d1 = fmaf(-2.0f, acc[mt][nt][1], cn.y);
                    if (d0 < minv[s0]) { minv[s0] = d0; mini[s0] = kk; }
                    if (d1 < minv[s0]) { minv[s0] = d1; mini[s0] = kk + 1; }
                    float d2 = fmaf(-2.0f, acc[mt][nt][2], cn.x);
                    float d3 = fmaf(-2.0f, acc[mt][nt][3], cn.y);
                    if (d2 < minv[s0 + 1]) { minv[s0 + 1] = d2; mini[s0 + 1] = kk; }
                    if (d3 < minv[s0 + 1]) { minv[s0 + 1] = d3; mini[s0 + 1] = kk + 1; }
                }
            }
        }
        __syncthreads();
    }

    // ---- final reduce. Quad shuffle (lanes sharing a row), then across wn via SMEM.
    float* rv = cnorm_s;                 // reuse (cnorm no longer needed)
    int*   ri = (int*)(cnorm_s + 512);
    #pragma unroll
    for (int s2 = 0; s2 < 8; s2++) {
        float v = minv[s2];
        int   i = mini[s2];
        #pragma unroll
        for (int off = 1; off <= 2; off <<= 1) {
            float ov = __shfl_xor_sync(0xffffffffu, v, off);
            int   oi = __shfl_xor_sync(0xffffffffu, i, off);
            if (ov < v || (ov == v && oi < i)) { v = ov; i = oi; }
        }
        if ((lane & 3) == 0) {
            int row = wm * 64 + (s2 >> 1) * 16 + (s2 & 1) * 8 + (lane >> 2);
            rv[row * 4 + wn] = v;
            ri[row * 4 + wn] = i;
        }
    }
    __syncthreads();
    if (tid < MTILE) {
        float bv = rv[tid * 4];
        int   bi = ri[tid * 4];
        #pragma unroll
        for (int t = 1; t < 4; t++) {
            float v = rv[tid * 4 + t];
            int  ii = ri[tid * 4 + t];
            if (v < bv || (v == bv && ii < bi)) { bv = v; bi = ii; }
        }
        g_idx[pbase + tid] = bi;
    }
}

// ---------------------------------------------------------------- downstream
__global__ void accum_kernel(const float* __restrict__ z) {
    int n = blockIdx.x, d = threadIdx.x;
    int idx = g_idx[n];
    int b = n >> 10, hw = n & (HWSZ - 1);
    float zv = z[((size_t)b * DDIM + d) * HWSZ + hw];
    atomicAdd(&g_dw[idx * DDIM + d], zv);
    if (d == 0) atomicAdd(&g_counts[idx], 1.0f);
}

__global__ void finalize_kernel(const float* __restrict__ ema_count,
                                const float* __restrict__ ema_weight,
                                float* __restrict__ out) {
    int k = blockIdx.x, d = threadIdx.x;
    float cnt = ema_count[k] * 0.99f + 0.01f * g_counts[k];
    float w = ema_weight[(size_t)k * DDIM + d] * 0.99f + 0.01f * g_dw[(size_t)k * DDIM + d];
    out[O_WT + (size_t)k * DDIM + d] = w;
    out[O_CB + (size_t)k * DDIM + d] = w / fmaxf(cnt, 1.0f);
    if (d == 0) out[O_CNT + k] = cnt;
}

__global__ void zq_kernel(const float* __restrict__ z,
                          const float* __restrict__ cb,
                          float* __restrict__ out) {
    int bd = blockIdx.x;
    int b = bd >> 7, d = bd & 127;
    for (int hw = threadIdx.x; hw < HWSZ; hw += blockDim.x) {
        int n = b * HWSZ + hw;
        float ze = z[(size_t)bd * HWSZ + hw];
        float zq = cb[(size_t)g_idx[n] * DDIM + d];
        out[O_ZQ + (size_t)bd * HWSZ + hw] = ze + (zq - ze);
    }
}

__global__ void idxout_kernel(float* __restrict__ out) {
    int n = blockIdx.x * blockDim.x + threadIdx.x;
    if (n < NPTS) out[O_IDX + n] = (float)g_idx[n];
}

// ---------------------------------------------------------------- launch
extern "C" void kernel_launch(void* const* d_in, const int* in_sizes, int n_in,
                              void* d_out, int out_size) {
    const float* z_e        = (const float*)d_in[0];
    const float* codebook   = (const float*)d_in[1];
    const float* ema_count  = (const float*)d_in[2];
    const float* ema_weight = (const float*)d_in[3];
    float* out = (float*)d_out;

    const int SMEM_DYN = MTILE * ZSTRIDE * 2 + 2 * BUFB + KCODES * 4;  // 206848
    static int smem_set = 0;
    if (!smem_set) {
        cudaFuncSetAttribute(argmin_kernel, cudaFuncAttributeMaxDynamicSharedMemorySize, SMEM_DYN);
        smem_set = 1;
    }

    prep_kernel<<<KCODES, 128>>>(codebook);
    bext_kernel<<<(KCODES * DDIM) / 256, 256>>>(codebook);
    argmin_kernel<<<NPTS / MTILE, 256, SMEM_DYN>>>(z_e);
    accum_kernel<<<NPTS, 128>>>(z_e);
    finalize_kernel<<<KCODES, 128>>>(ema_count, ema_weight, out);
    zq_kernel<<<2048, 256>>>(z_e, codebook, out);
    idxout_kernel<<<(NPTS + 255) / 256, 256>>>(out);
}